// round 7
// baseline (speedup 1.0000x reference)
#include <cuda_runtime.h>
#include <cuda_fp16.h>

#define Nn 100000
#define MAXE 3200000
#define Gg 5000
#define BN_EPS 1e-5f

// ---------------- scratch (static device globals) ----------------
__device__ int      g_deg [Nn];
__device__ int      g_row [Nn + 1];
__device__ int      g_cur [Nn];
__device__ int      g_csrc[MAXE];
__device__ float    g_dinv[Nn];
__device__ uint4    g_xh  [Nn * 4];     // x' = x*dinv, padded to 32 halfs
__device__ float    g_axp [Nn * 32];    // aggregated x', padded 32 floats
__device__ uint4    g_t2h [Nn * 4];     // t2' = bnrelu(acc1)@W2*dinv, 32 halfs
__device__ uint4    g_t3h [Nn * 2];     // t3' = bnrelu(acc2)@W3*dinv, 16 halfs
__device__ uint4    g_h3h [Nn * 2];     // h3 post-BN, 16 halfs
__device__ float    g_acc1[Nn * 64];
__device__ float    g_acc2[Nn * 32];
__device__ float    g_acc3[Nn * 16];
__device__ float    g_as  [Nn * 8];
__device__ float    g_ad  [Nn * 8];
__device__ float    g_was [16 * 8];
__device__ float    g_wad [16 * 8];
__device__ float    g_pool[Gg * 16];
__device__ float    g_bn  [6 * 64];     // [sum|sumsq] per layer: L1@0, L2@128, L3@256

// ---------------- helpers ----------------
__device__ __forceinline__ void red4(float4* p, float4 v) {
    asm volatile("red.global.add.v4.f32 [%0], {%1,%2,%3,%4};"
                 :: "l"(p), "f"(v.x), "f"(v.y), "f"(v.z), "f"(v.w) : "memory");
}
__device__ __forceinline__ float leaky(float v) { return v > 0.f ? v : 0.2f * v; }
__device__ __forceinline__ void acc8(float* a, uint4 u) {
    const __half2* h = (const __half2*)&u;
    float2 f0 = __half22float2(h[0]); a[0] += f0.x; a[1] += f0.y;
    float2 f1 = __half22float2(h[1]); a[2] += f1.x; a[3] += f1.y;
    float2 f2 = __half22float2(h[2]); a[4] += f2.x; a[5] += f2.y;
    float2 f3 = __half22float2(h[3]); a[6] += f3.x; a[7] += f3.y;
}

// ---------------- CSR build ----------------
__global__ void k_init() {
    int T = gridDim.x * blockDim.x;
    for (int i = blockIdx.x * blockDim.x + threadIdx.x; i < Nn; i += T) {
        g_deg[i] = 0;
        if (i < Gg * 16) g_pool[i] = 0.f;
        if (i < 6 * 64)  g_bn[i] = 0.f;
    }
}

__global__ void k_deg(const int* __restrict__ ei, int E) {
    int t = blockIdx.x * blockDim.x + threadIdx.x;
    int i0 = t * 4;
    if (i0 + 3 < E) {
        int4 d4 = *(const int4*)(ei + E + i0);
        atomicAdd(&g_deg[d4.x], 1); atomicAdd(&g_deg[d4.y], 1);
        atomicAdd(&g_deg[d4.z], 1); atomicAdd(&g_deg[d4.w], 1);
    } else {
        for (int i = i0; i < E; i++) atomicAdd(&g_deg[ei[E + i]], 1);
    }
}

// single-block coalesced scan over g_deg -> g_row (exclusive); g_cur, g_dinv
__global__ void k_scan() {
    __shared__ int wsum[32];
    int t = threadIdx.x, lane = t & 31, w = t >> 5;
    int carry = 0;
    for (int base = 0; base < Nn; base += 1024) {
        int idx = base + t;
        int v = (idx < Nn) ? g_deg[idx] : 0;
        int x = v;
#pragma unroll
        for (int off = 1; off < 32; off <<= 1) {
            int y = __shfl_up_sync(~0u, x, off);
            if (lane >= off) x += y;
        }
        if (lane == 31) wsum[w] = x;
        __syncthreads();
        if (w == 0) {
            int s = wsum[lane];
#pragma unroll
            for (int off = 1; off < 32; off <<= 1) {
                int y = __shfl_up_sync(~0u, s, off);
                if (lane >= off) s += y;
            }
            wsum[lane] = s;
        }
        __syncthreads();
        int woff = (w == 0) ? 0 : wsum[w - 1];
        int excl = carry + woff + x - v;
        if (idx < Nn) {
            g_row[idx] = excl;
            g_cur[idx] = excl;
            g_dinv[idx] = rsqrtf((float)(v + 1));  // +1 self loop
        }
        int tot = wsum[31];
        __syncthreads();
        carry += tot;
    }
    if (t == 0) g_row[Nn] = carry;
}

__global__ void k_fill(const int* __restrict__ ei, int E) {
    int t = blockIdx.x * blockDim.x + threadIdx.x;
    int i0 = t * 4;
    if (i0 + 3 < E) {
        int4 s4 = *(const int4*)(ei + i0);
        int4 d4 = *(const int4*)(ei + E + i0);
        int p0 = atomicAdd(&g_cur[d4.x], 1);
        int p1 = atomicAdd(&g_cur[d4.y], 1);
        int p2 = atomicAdd(&g_cur[d4.z], 1);
        int p3 = atomicAdd(&g_cur[d4.w], 1);
        g_csrc[p0] = s4.x; g_csrc[p1] = s4.y; g_csrc[p2] = s4.z; g_csrc[p3] = s4.w;
    } else {
        for (int i = i0; i < E; i++) {
            int p = atomicAdd(&g_cur[ei[E + i]], 1);
            g_csrc[p] = ei[i];
        }
    }
}

// x'[n][c] = x[n][c]*dinv[n], zero-padded to 32 halfs
__global__ void k_convx(const float* __restrict__ x) {
    int i = blockIdx.x * blockDim.x + threadIdx.x;
    if (i >= Nn * 32) return;
    int node = i >> 5, c = i & 31;
    float v = (c < 20) ? x[node * 20 + c] * g_dinv[node] : 0.f;
    ((__half*)g_xh)[i] = __float2half_rn(v);
}

// ---------------- GCN CSR gather: WARP PER NODE, edge-parallel ----------------
// row = U4 uint4 (U4*8 halfs). 32/U4 edge slots walk the node's list in parallel;
// shuffle-butterfly merges slot partials. out[d] = dinv[d]*(sum_adj + self) + b.
// Grid must be exactly Nn/(blockDim/32) blocks (no early return; STATS syncs).
template <int U4, bool STATS>
__global__ void k_gcn(const uint4* __restrict__ rows, const float* __restrict__ b,
                      float4* __restrict__ out4, float* __restrict__ stat) {
    const int F = U4 * 8;
    const int NE = 32 / U4;              // edge slots per warp
    __shared__ float ss[F], sq[F];
    if (STATS) {
        if (threadIdx.x < F) { ss[threadIdx.x] = 0.f; sq[threadIdx.x] = 0.f; }
        __syncthreads();
    }
    int lane = threadIdx.x & 31, warp = threadIdx.x >> 5;
    int node = blockIdx.x * (blockDim.x >> 5) + warp;   // always < Nn (exact grid)
    int e = lane / U4, j = lane % U4;
    float di = g_dinv[node];
    int r0 = g_row[node], r1 = g_row[node + 1];
    float a[8] = {0, 0, 0, 0, 0, 0, 0, 0};
    int k = r0 + e;
    if (k < r1) {
        int s = __ldg(&g_csrc[k]);
        k += NE;
        while (k < r1) {
            int sn = __ldg(&g_csrc[k]);
            acc8(a, __ldg(&rows[s * U4 + j]));
            s = sn;
            k += NE;
        }
        acc8(a, __ldg(&rows[s * U4 + j]));
    }
    // merge edge slots (lanes with equal j)
#pragma unroll
    for (int off = U4; off < 32; off <<= 1) {
#pragma unroll
        for (int c = 0; c < 8; c++) a[c] += __shfl_xor_sync(~0u, a[c], off);
    }
    if (e == 0) {
        acc8(a, __ldg(&rows[node * U4 + j]));  // self
        float4 b0 = b ? __ldg(&((const float4*)b)[j * 2])     : make_float4(0, 0, 0, 0);
        float4 b1 = b ? __ldg(&((const float4*)b)[j * 2 + 1]) : make_float4(0, 0, 0, 0);
        float o[8];
#pragma unroll
        for (int c = 0; c < 8; c++) {
            float bb = (c < 4) ? (&b0.x)[c] : (&b1.x)[c - 4];
            o[c] = a[c] * di + bb;
        }
        out4[node * (U4 * 2) + j * 2]     = make_float4(o[0], o[1], o[2], o[3]);
        out4[node * (U4 * 2) + j * 2 + 1] = make_float4(o[4], o[5], o[6], o[7]);
        if (STATS) {
#pragma unroll
            for (int c = 0; c < 8; c++) {
                atomicAdd(&ss[j * 8 + c], o[c]);
                atomicAdd(&sq[j * 8 + c], o[c] * o[c]);
            }
        }
    }
    if (STATS) {
        __syncthreads();
        if (threadIdx.x < F) {
            atomicAdd(&stat[threadIdx.x], ss[threadIdx.x]);
            atomicAdd(&stat[F + threadIdx.x], sq[threadIdx.x]);
        }
    }
}

// ---------------- GEMM layer 1: axp(20 of 32) @ W1 + b1 -> acc1, with stats ----------------
__global__ void k_gemm1(const float* __restrict__ h, const float* __restrict__ W,
                        const float* __restrict__ bias, float* __restrict__ out,
                        float* __restrict__ stat) {
    __shared__ float Ws[20 * 64];
    __shared__ float ss[64], sq[64];
    int tid = threadIdx.x;
    for (int i = tid; i < 20 * 64; i += 512) Ws[i] = W[i];
    if (tid < 64) { ss[tid] = 0.f; sq[tid] = 0.f; }
    __syncthreads();
    int fo = tid & 63, r = tid >> 6;
    int node = blockIdx.x * 8 + r;                 // 100000/8 = 12500 exact
    const float* hr = h + node * 32;
    float a = bias[fo];
#pragma unroll
    for (int fi = 0; fi < 20; fi++) a += hr[fi] * Ws[fi * 64 + fo];
    out[node * 64 + fo] = a;
    atomicAdd(&ss[fo], a);
    atomicAdd(&sq[fo], a * a);
    __syncthreads();
    if (tid < 64) {
        atomicAdd(&stat[tid], ss[tid]);
        atomicAdd(&stat[64 + tid], sq[tid]);
    }
}

// ---------------- fused BN+ReLU + GEMM + *dinv -> half ----------------
template <int FI, int FO>
__global__ void k_gemmbn(const float* __restrict__ acc, const float* __restrict__ stat,
                         const float* __restrict__ g, const float* __restrict__ be,
                         const float* __restrict__ W, __half* __restrict__ out) {
    const int BLK = 512;
    const int ROWS = BLK / FO;
    __shared__ float Ws[FI * FO];
    __shared__ float Hs[ROWS * FI];
    __shared__ float sc[FI], sh[FI];
    int tid = threadIdx.x;
    for (int i = tid; i < FI * FO; i += BLK) Ws[i] = W[i];
    if (tid < FI) {
        const float invn = 1.0f / (float)Nn;
        float mu  = stat[tid] * invn;
        float var = stat[FI + tid] * invn - mu * mu;
        float kk  = g[tid] * rsqrtf(var + BN_EPS);
        sc[tid] = kk;
        sh[tid] = be[tid] - mu * kk;
    }
    __syncthreads();
    int node0 = blockIdx.x * ROWS;
    for (int i = tid; i < ROWS * FI; i += BLK) {
        int r = i / FI, f = i % FI;
        Hs[i] = fmaxf(acc[(node0 + r) * FI + f] * sc[f] + sh[f], 0.f);
    }
    __syncthreads();
    int fo = tid % FO, r = tid / FO;
    int node = node0 + r;
    float a = 0.f;
#pragma unroll
    for (int fi = 0; fi < FI; fi++) a += Hs[r * FI + fi] * Ws[fi * FO + fo];
    a *= g_dinv[node];
    out[node * FO + fo] = __float2half_rn(a);
}

// was[k][h] = sum_c Wg[k][h*16+c]*att_src[h][c]; wad likewise. 128 threads.
__global__ void k_prep(const float* __restrict__ Wg, const float* __restrict__ asrc,
                       const float* __restrict__ adst) {
    int t = threadIdx.x;
    int k = t >> 3, h = t & 7;
    float s1 = 0.f, s2 = 0.f;
#pragma unroll
    for (int c = 0; c < 16; c++) {
        float w = Wg[k * 128 + h * 16 + c];
        s1 += w * asrc[h * 16 + c];
        s2 += w * adst[h * 16 + c];
    }
    g_was[k * 8 + h] = s1;
    g_wad[k * 8 + h] = s2;
}

// fused BN+ReLU(layer3) + h3->half + attention dots. block=256 -> 16 nodes. Nn%16==0.
__global__ void k_bn3att(const float* __restrict__ acc3, const float* __restrict__ stat,
                         const float* __restrict__ g, const float* __restrict__ be) {
    __shared__ float sv[16][17];
    __shared__ float sw[2][16][8];
    int t = threadIdx.x;
    if (t < 128) { sw[0][t >> 3][t & 7] = g_was[t]; sw[1][t >> 3][t & 7] = g_wad[t]; }
    int node0 = blockIdx.x * 16;
    int nl = t >> 4, f = t & 15;
    const float invn = 1.0f / (float)Nn;
    float mu  = stat[f] * invn;
    float var = stat[16 + f] * invn - mu * mu;
    float v = (acc3[(node0 + nl) * 16 + f] - mu) * rsqrtf(var + BN_EPS) * g[f] + be[f];
    v = fmaxf(v, 0.f);
    sv[nl][f] = v;
    __syncthreads();
    if (t < 64) {
        int n2 = t >> 2, q = t & 3;
        __half2 p0 = __floats2half2_rn(sv[n2][q * 4 + 0], sv[n2][q * 4 + 1]);
        __half2 p1 = __floats2half2_rn(sv[n2][q * 4 + 2], sv[n2][q * 4 + 3]);
        uint2 u;
        u.x = *(unsigned*)&p0;
        u.y = *(unsigned*)&p1;
        ((uint2*)g_h3h)[(node0 + n2) * 4 + q] = u;
    }
    if (t < 128) {
        int n3 = t >> 3, h = t & 7;
        float s1 = 0.f, s2 = 0.f;
#pragma unroll
        for (int k = 0; k < 16; k++) {
            float hv = sv[n3][k];
            s1 += hv * sw[0][k][h];
            s2 += hv * sw[1][k][h];
        }
        g_as[(node0 + n3) * 8 + h] = s1;
        g_ad[(node0 + n3) * 8 + h] = s2;
    }
}

// ---------------- fused GAT: warp per node, 2 online-softmax edge slots ----------------
__device__ __forceinline__ void gat_step8(float l, uint4 u, float& m, float& sum, float* acc) {
    const __half2* hp = (const __half2*)&u;
    float f[8];
    float2 t0 = __half22float2(hp[0]); f[0] = t0.x; f[1] = t0.y;
    float2 t1 = __half22float2(hp[1]); f[2] = t1.x; f[3] = t1.y;
    float2 t2 = __half22float2(hp[2]); f[4] = t2.x; f[5] = t2.y;
    float2 t3 = __half22float2(hp[3]); f[6] = t3.x; f[7] = t3.y;
    float d = l - m;
    float e = __expf(-fabsf(d));
    if (d <= 0.f) {
        sum += e;
#pragma unroll
        for (int c = 0; c < 8; c++) acc[c] += e * f[c];
    } else {
        sum = sum * e + 1.f;
#pragma unroll
        for (int c = 0; c < 8; c++) acc[c] = acc[c] * e + f[c];
        m = l;
    }
}

__global__ void k_gat(const float* __restrict__ Wg, const float* __restrict__ bg,
                      const int* __restrict__ batch) {
    __shared__ float Wgs[16 * 128];
    __shared__ float buf[8][8][16];     // [warp][head][k]
    for (int i = threadIdx.x; i < 16 * 128; i += blockDim.x) Wgs[i] = Wg[i];
    __syncthreads();
    int lane = threadIdx.x & 31, warp = threadIdx.x >> 5;
    int d = blockIdx.x * 8 + warp;      // grid = Nn/8 exact
    int e = lane >> 4;                  // edge slot 0/1
    int h = (lane >> 1) & 7;            // head
    int j = lane & 1;                   // feature half (8 halfs each)
    const uint4* h3 = g_h3h;
    float adh = g_ad[d * 8 + h];
    int r0 = g_row[d], r1 = g_row[d + 1];

    float m, sum, acc[8];
    if (e == 0) {   // slot 0 seeded with self edge
        m = leaky(g_as[d * 8 + h] + adh);
        sum = 1.f;
        uint4 u = __ldg(&h3[d * 2 + j]);
        const __half2* hp = (const __half2*)&u;
        float2 t0 = __half22float2(hp[0]); acc[0] = t0.x; acc[1] = t0.y;
        float2 t1 = __half22float2(hp[1]); acc[2] = t1.x; acc[3] = t1.y;
        float2 t2 = __half22float2(hp[2]); acc[4] = t2.x; acc[5] = t2.y;
        float2 t3 = __half22float2(hp[3]); acc[6] = t3.x; acc[7] = t3.y;
    } else {        // slot 1 neutral
        m = -1e30f; sum = 0.f;
#pragma unroll
        for (int c = 0; c < 8; c++) acc[c] = 0.f;
    }

    int k = r0 + e;
    if (k + 2 < r1) {
        int s0 = __ldg(&g_csrc[k]);
        int s1 = __ldg(&g_csrc[k + 2]);
        k += 4;
        while (k + 2 < r1) {
            int n0 = __ldg(&g_csrc[k]);
            int n1 = __ldg(&g_csrc[k + 2]);
            float l0 = leaky(__ldg(&g_as[s0 * 8 + h]) + adh);
            uint4 u0 = __ldg(&h3[s0 * 2 + j]);
            float l1 = leaky(__ldg(&g_as[s1 * 8 + h]) + adh);
            uint4 u1 = __ldg(&h3[s1 * 2 + j]);
            gat_step8(l0, u0, m, sum, acc);
            gat_step8(l1, u1, m, sum, acc);
            s0 = n0; s1 = n1; k += 4;
        }
        float l0 = leaky(__ldg(&g_as[s0 * 8 + h]) + adh);
        uint4 u0 = __ldg(&h3[s0 * 2 + j]);
        float l1 = leaky(__ldg(&g_as[s1 * 8 + h]) + adh);
        uint4 u1 = __ldg(&h3[s1 * 2 + j]);
        gat_step8(l0, u0, m, sum, acc);
        gat_step8(l1, u1, m, sum, acc);
    }
    if (k < r1) {
        int s = __ldg(&g_csrc[k]);
        float l = leaky(__ldg(&g_as[s * 8 + h]) + adh);
        gat_step8(l, __ldg(&h3[s * 2 + j]), m, sum, acc);
    }

    // merge the two slots (online-softmax combine across xor-16)
    float m_o   = __shfl_xor_sync(~0u, m, 16);
    float sum_o = __shfl_xor_sync(~0u, sum, 16);
    float mm = fmaxf(m, m_o);
    float es = __expf(m - mm), eo = __expf(m_o - mm);
    sum = sum * es + sum_o * eo;
#pragma unroll
    for (int c = 0; c < 8; c++) {
        float ao = __shfl_xor_sync(~0u, acc[c], 16);
        acc[c] = acc[c] * es + ao * eo;
    }
    float scale = 0.125f / sum;   // alpha-normalize + head-mean
    if (e == 0) {
#pragma unroll
        for (int c = 0; c < 8; c++) buf[warp][h][j * 8 + c] = acc[c] * scale;
    }
    __syncwarp();

    // mini-GEMM: hg[c] = bg[c] + sum_h sum_k buf[h][k]*Wg[k][h*16+c]; then pool
    if (lane < 4) {
        float4 hg = ((const float4*)bg)[lane];
#pragma unroll
        for (int hh = 0; hh < 8; hh++) {
#pragma unroll
            for (int kk = 0; kk < 16; kk++) {
                float a = buf[warp][hh][kk];
                const float4 w = *(const float4*)&Wgs[kk * 128 + hh * 16 + lane * 4];
                hg.x += a * w.x; hg.y += a * w.y; hg.z += a * w.z; hg.w += a * w.w;
            }
        }
        red4(((float4*)g_pool) + batch[d] * 4 + lane, hg);
    }
}

__global__ void k_final(const float* __restrict__ Wf, const float* __restrict__ bf,
                        float* __restrict__ out) {
    int i = blockIdx.x * blockDim.x + threadIdx.x;
    if (i >= Gg * 3) return;
    int gg = i / 3, k = i % 3;
    float s = bf[k];
#pragma unroll
    for (int c = 0; c < 16; c++) s += g_pool[gg * 16 + c] * Wf[c * 3 + k];
    out[i] = s;
}

// ---------------- launch ----------------
static inline void* symaddr(const void* s) { void* p = nullptr; cudaGetSymbolAddress(&p, s); return p; }

extern "C" void kernel_launch(void* const* d_in, const int* in_sizes, int n_in,
                              void* d_out, int out_size) {
    const float* x       = (const float*)d_in[0];
    const int*   ei      = (const int*)  d_in[1];
    const int*   batch   = (const int*)  d_in[2];
    const float* W1 = (const float*)d_in[3],  *b1 = (const float*)d_in[4];
    const float* g1 = (const float*)d_in[5],  *be1= (const float*)d_in[6];
    const float* W2 = (const float*)d_in[7],  *b2 = (const float*)d_in[8];
    const float* g2 = (const float*)d_in[9],  *be2= (const float*)d_in[10];
    const float* W3 = (const float*)d_in[11], *b3 = (const float*)d_in[12];
    const float* g3 = (const float*)d_in[13], *be3= (const float*)d_in[14];
    const float* Wg = (const float*)d_in[15];
    const float* att_src = (const float*)d_in[16];
    const float* att_dst = (const float*)d_in[17];
    const float* bg = (const float*)d_in[18];
    const float* Wf = (const float*)d_in[19], *bf = (const float*)d_in[20];
    float* out = (float*)d_out;
    const int E = in_sizes[1] / 2;

    float* axp  = (float*)symaddr(g_axp);
    float* acc1 = (float*)symaddr(g_acc1);
    float* acc2 = (float*)symaddr(g_acc2);
    float* acc3 = (float*)symaddr(g_acc3);
    float* bn   = (float*)symaddr(g_bn);
    uint4* xh   = (uint4*)symaddr(g_xh);
    uint4* t2h  = (uint4*)symaddr(g_t2h);
    uint4* t3h  = (uint4*)symaddr(g_t3h);

    const int B = 256;
    // ---- CSR build ----
    k_init<<<(Nn + B - 1) / B, B>>>();
    k_deg<<<(E / 4 + B) / B, B>>>(ei, E);
    k_scan<<<1, 1024>>>();
    k_fill<<<(E / 4 + B) / B, B>>>(ei, E);
    k_convx<<<(Nn * 32 + B - 1) / B, B>>>(x);

    // ---- GCN layer 1: aggregate x' (warp/node), GEMM 20->64 (+stats) ----
    k_gcn<4, false><<<Nn / 8, B>>>(xh, nullptr, (float4*)axp, nullptr);
    k_gemm1<<<Nn / 8, 512>>>(axp, W1, b1, acc1, bn + 0);

    // ---- GCN layer 2: fused BN1+ReLU+GEMM 64->32 (*dinv, half), aggregate (+stats) ----
    k_gemmbn<64, 32><<<Nn / 16, 512>>>(acc1, bn + 0, g1, be1, W2, (__half*)t2h);
    k_gcn<4, true><<<Nn / 8, B>>>(t2h, b2, (float4*)acc2, bn + 128);

    // ---- GCN layer 3: fused BN2+ReLU+GEMM 32->16 (*dinv, half), aggregate (+stats) ----
    k_gemmbn<32, 16><<<Nn / 32, 512>>>(acc2, bn + 128, g2, be2, W3, (__half*)t3h);
    k_gcn<2, true><<<Nn / 8, B>>>(t3h, b3, (float4*)acc3, bn + 256);

    // ---- BN3 + attention dots fused, then single-pass GAT ----
    k_prep<<<1, 128>>>(Wg, att_src, att_dst);
    k_bn3att<<<Nn / 16, B>>>(acc3, bn + 256, g3, be3);
    k_gat<<<Nn / 8, B>>>(Wg, bg, batch);

    // ---- classifier ----
    k_final<<<(Gg * 3 + B - 1) / B, B>>>(Wf, bf, out);
}

// round 8
// speedup vs baseline: 1.1312x; 1.1312x over previous
#include <cuda_runtime.h>
#include <cuda_fp16.h>

#define Nn 100000
#define MAXE 3200000
#define Gg 5000
#define BN_EPS 1e-5f

// ---------------- scratch (static device globals) ----------------
__device__ int      g_deg [Nn];
__device__ int      g_row [Nn + 1];
__device__ int      g_cur [Nn];
__device__ int      g_csrc[MAXE];
__device__ float    g_dinv[Nn];
__device__ uint4    g_xh  [Nn * 4];     // x' = x*dinv, padded to 32 halfs
__device__ float    g_axp [Nn * 32];    // aggregated x', padded 32 floats
__device__ uint4    g_t2h [Nn * 4];     // t2' = bnrelu(acc1)@W2*dinv, 32 halfs
__device__ uint4    g_t3h [Nn * 2];     // t3' = bnrelu(acc2)@W3*dinv, 16 halfs
__device__ uint2    g_h3h [Nn * 4];     // h3 post-BN, 16 halfs
__device__ float    g_acc1[Nn * 64];
__device__ float    g_acc2[Nn * 32];
__device__ float    g_acc3[Nn * 16];
__device__ float    g_as  [Nn * 8];
__device__ float    g_ad  [Nn * 8];
__device__ float    g_was [16 * 8];
__device__ float    g_wad [16 * 8];
__device__ float    g_pool[Gg * 16];
__device__ float    g_bn  [6 * 64];     // [sum|sumsq] per layer: L1@0, L2@128, L3@256

// ---------------- helpers ----------------
__device__ __forceinline__ void red4(float4* p, float4 v) {
    asm volatile("red.global.add.v4.f32 [%0], {%1,%2,%3,%4};"
                 :: "l"(p), "f"(v.x), "f"(v.y), "f"(v.z), "f"(v.w) : "memory");
}
__device__ __forceinline__ float leaky(float v) { return v > 0.f ? v : 0.2f * v; }
__device__ __forceinline__ void acc8(float* a, uint4 u) {
    const __half2* h = (const __half2*)&u;
    float2 f0 = __half22float2(h[0]); a[0] += f0.x; a[1] += f0.y;
    float2 f1 = __half22float2(h[1]); a[2] += f1.x; a[3] += f1.y;
    float2 f2 = __half22float2(h[2]); a[4] += f2.x; a[5] += f2.y;
    float2 f3 = __half22float2(h[3]); a[6] += f3.x; a[7] += f3.y;
}

// ---------------- CSR build ----------------
__global__ void k_init() {
    int T = gridDim.x * blockDim.x;
    for (int i = blockIdx.x * blockDim.x + threadIdx.x; i < Nn; i += T) {
        g_deg[i] = 0;
        if (i < Gg * 16) g_pool[i] = 0.f;
        if (i < 6 * 64)  g_bn[i] = 0.f;
    }
}

__global__ void k_deg(const int* __restrict__ ei, int E) {
    int t = blockIdx.x * blockDim.x + threadIdx.x;
    int i0 = t * 4;
    if (i0 + 3 < E) {
        int4 d4 = *(const int4*)(ei + E + i0);
        atomicAdd(&g_deg[d4.x], 1); atomicAdd(&g_deg[d4.y], 1);
        atomicAdd(&g_deg[d4.z], 1); atomicAdd(&g_deg[d4.w], 1);
    } else {
        for (int i = i0; i < E; i++) atomicAdd(&g_deg[ei[E + i]], 1);
    }
}

// single-block coalesced scan over g_deg -> g_row (exclusive); g_cur, g_dinv
__global__ void k_scan() {
    __shared__ int wsum[32];
    int t = threadIdx.x, lane = t & 31, w = t >> 5;
    int carry = 0;
    for (int base = 0; base < Nn; base += 1024) {
        int idx = base + t;
        int v = (idx < Nn) ? g_deg[idx] : 0;
        int x = v;
#pragma unroll
        for (int off = 1; off < 32; off <<= 1) {
            int y = __shfl_up_sync(~0u, x, off);
            if (lane >= off) x += y;
        }
        if (lane == 31) wsum[w] = x;
        __syncthreads();
        if (w == 0) {
            int s = wsum[lane];
#pragma unroll
            for (int off = 1; off < 32; off <<= 1) {
                int y = __shfl_up_sync(~0u, s, off);
                if (lane >= off) s += y;
            }
            wsum[lane] = s;
        }
        __syncthreads();
        int woff = (w == 0) ? 0 : wsum[w - 1];
        int excl = carry + woff + x - v;
        if (idx < Nn) {
            g_row[idx] = excl;
            g_cur[idx] = excl;
            g_dinv[idx] = rsqrtf((float)(v + 1));  // +1 self loop
        }
        int tot = wsum[31];
        __syncthreads();
        carry += tot;
    }
    if (t == 0) g_row[Nn] = carry;
}

__global__ void k_fill(const int* __restrict__ ei, int E) {
    int t = blockIdx.x * blockDim.x + threadIdx.x;
    int i0 = t * 4;
    if (i0 + 3 < E) {
        int4 s4 = *(const int4*)(ei + i0);
        int4 d4 = *(const int4*)(ei + E + i0);
        int p0 = atomicAdd(&g_cur[d4.x], 1);
        int p1 = atomicAdd(&g_cur[d4.y], 1);
        int p2 = atomicAdd(&g_cur[d4.z], 1);
        int p3 = atomicAdd(&g_cur[d4.w], 1);
        g_csrc[p0] = s4.x; g_csrc[p1] = s4.y; g_csrc[p2] = s4.z; g_csrc[p3] = s4.w;
    } else {
        for (int i = i0; i < E; i++) {
            int p = atomicAdd(&g_cur[ei[E + i]], 1);
            g_csrc[p] = ei[i];
        }
    }
}

// x'[n][c] = x[n][c]*dinv[n], zero-padded to 32 halfs
__global__ void k_convx(const float* __restrict__ x) {
    int i = blockIdx.x * blockDim.x + threadIdx.x;
    if (i >= Nn * 32) return;
    int node = i >> 5, c = i & 31;
    float v = (c < 20) ? x[node * 20 + c] * g_dinv[node] : 0.f;
    ((__half*)g_xh)[i] = __float2half_rn(v);
}

// ---------------- GCN CSR gather (half rows, dinv pre-folded, 2-stage pipeline) ----------------
// row = U4 uint4 (U4*8 halfs). Group of U4 lanes per node, 32/U4 nodes per warp.
// 2-stage: fetch idx batch n+2, issue rows batch n+1, accumulate batch n.
template <int U4, bool STATS>
__global__ void k_gcn(const uint4* __restrict__ rows, const float* __restrict__ b,
                      float4* __restrict__ out4, float* __restrict__ stat) {
    const int F = U4 * 8;
    __shared__ float ss[F], sq[F];
    if (STATS) {
        if (threadIdx.x < F) { ss[threadIdx.x] = 0.f; sq[threadIdx.x] = 0.f; }
        __syncthreads();
    }
    const int GPW = 32 / U4;
    int lane = threadIdx.x & 31, warp = threadIdx.x >> 5;
    int grp = lane / U4, j = lane % U4;
    int node = (blockIdx.x * (blockDim.x >> 5) + warp) * GPW + grp;
    bool act = node < Nn;
    float a[8] = {0, 0, 0, 0, 0, 0, 0, 0};
    float di = 0.f;
    int r0 = 0, r1 = 0;
    if (act) {
        di = g_dinv[node];
        r0 = g_row[node];
        r1 = g_row[node + 1];
        acc8(a, __ldg(&rows[node * U4 + j]));  // self
    }
    int nb = (r1 - r0) >> 2;
    int k = r0 + (nb << 2);          // tail start
    if (nb >= 2) {
        int p0 = __ldg(&g_csrc[r0]),     p1 = __ldg(&g_csrc[r0 + 1]);
        int p2 = __ldg(&g_csrc[r0 + 2]), p3 = __ldg(&g_csrc[r0 + 3]);
        int q0 = __ldg(&g_csrc[r0 + 4]), q1 = __ldg(&g_csrc[r0 + 5]);
        int q2 = __ldg(&g_csrc[r0 + 6]), q3 = __ldg(&g_csrc[r0 + 7]);
        uint4 va0 = __ldg(&rows[p0 * U4 + j]);
        uint4 va1 = __ldg(&rows[p1 * U4 + j]);
        uint4 va2 = __ldg(&rows[p2 * U4 + j]);
        uint4 va3 = __ldg(&rows[p3 * U4 + j]);
        for (int t = 0; t < nb - 1; t++) {
            int c0, c1, c2, c3;
            bool more = (t + 2) < nb;
            if (more) {
                int base = r0 + (t + 2) * 4;
                c0 = __ldg(&g_csrc[base]);     c1 = __ldg(&g_csrc[base + 1]);
                c2 = __ldg(&g_csrc[base + 2]); c3 = __ldg(&g_csrc[base + 3]);
            }
            uint4 vb0 = __ldg(&rows[q0 * U4 + j]);
            uint4 vb1 = __ldg(&rows[q1 * U4 + j]);
            uint4 vb2 = __ldg(&rows[q2 * U4 + j]);
            uint4 vb3 = __ldg(&rows[q3 * U4 + j]);
            acc8(a, va0); acc8(a, va1); acc8(a, va2); acc8(a, va3);
            va0 = vb0; va1 = vb1; va2 = vb2; va3 = vb3;
            if (more) { q0 = c0; q1 = c1; q2 = c2; q3 = c3; }
        }
        acc8(a, va0); acc8(a, va1); acc8(a, va2); acc8(a, va3);
    } else if (nb == 1) {
        int p0 = __ldg(&g_csrc[r0]),     p1 = __ldg(&g_csrc[r0 + 1]);
        int p2 = __ldg(&g_csrc[r0 + 2]), p3 = __ldg(&g_csrc[r0 + 3]);
        acc8(a, __ldg(&rows[p0 * U4 + j]));
        acc8(a, __ldg(&rows[p1 * U4 + j]));
        acc8(a, __ldg(&rows[p2 * U4 + j]));
        acc8(a, __ldg(&rows[p3 * U4 + j]));
    }
    for (; k < r1; k++) acc8(a, __ldg(&rows[__ldg(&g_csrc[k]) * U4 + j]));

    float o[8];
    float4 b0 = b ? __ldg(&((const float4*)b)[j * 2])     : make_float4(0, 0, 0, 0);
    float4 b1 = b ? __ldg(&((const float4*)b)[j * 2 + 1]) : make_float4(0, 0, 0, 0);
#pragma unroll
    for (int c = 0; c < 8; c++) {
        float bb = (c < 4) ? (&b0.x)[c] : (&b1.x)[c - 4];
        o[c] = act ? (a[c] * di + bb) : 0.f;
    }
    if (act) {
        out4[node * (U4 * 2) + j * 2]     = make_float4(o[0], o[1], o[2], o[3]);
        out4[node * (U4 * 2) + j * 2 + 1] = make_float4(o[4], o[5], o[6], o[7]);
    }
    if (STATS) {
        // butterfly-reduce over the GPW groups (lanes with same j)
        float q[8];
#pragma unroll
        for (int c = 0; c < 8; c++) q[c] = o[c] * o[c];
#pragma unroll
        for (int off = U4; off < 32; off <<= 1) {
#pragma unroll
            for (int c = 0; c < 8; c++) {
                o[c] += __shfl_xor_sync(~0u, o[c], off);
                q[c] += __shfl_xor_sync(~0u, q[c], off);
            }
        }
        if (grp == 0) {
#pragma unroll
            for (int c = 0; c < 8; c++) {
                atomicAdd(&ss[j * 8 + c], o[c]);
                atomicAdd(&sq[j * 8 + c], q[c]);
            }
        }
        __syncthreads();
        if (threadIdx.x < F) {
            atomicAdd(&stat[threadIdx.x], ss[threadIdx.x]);
            atomicAdd(&stat[F + threadIdx.x], sq[threadIdx.x]);
        }
    }
}

// ---------------- GEMM layer 1: axp(20 of 32) @ W1 + b1 -> acc1, with stats ----------------
__global__ void k_gemm1(const float* __restrict__ h, const float* __restrict__ W,
                        const float* __restrict__ bias, float* __restrict__ out,
                        float* __restrict__ stat) {
    __shared__ float Ws[20 * 64];
    __shared__ float ss[64], sq[64];
    int tid = threadIdx.x;
    for (int i = tid; i < 20 * 64; i += 512) Ws[i] = W[i];
    if (tid < 64) { ss[tid] = 0.f; sq[tid] = 0.f; }
    __syncthreads();
    int fo = tid & 63, r = tid >> 6;
    int node = blockIdx.x * 8 + r;                 // 100000/8 = 12500 exact
    const float* hr = h + node * 32;
    float a = bias[fo];
#pragma unroll
    for (int fi = 0; fi < 20; fi++) a += hr[fi] * Ws[fi * 64 + fo];
    out[node * 64 + fo] = a;
    atomicAdd(&ss[fo], a);
    atomicAdd(&sq[fo], a * a);
    __syncthreads();
    if (tid < 64) {
        atomicAdd(&stat[tid], ss[tid]);
        atomicAdd(&stat[64 + tid], sq[tid]);
    }
}

// ---------------- fused BN+ReLU + GEMM + *dinv -> half ----------------
template <int FI, int FO>
__global__ void k_gemmbn(const float* __restrict__ acc, const float* __restrict__ stat,
                         const float* __restrict__ g, const float* __restrict__ be,
                         const float* __restrict__ W, __half* __restrict__ out) {
    const int BLK = 512;
    const int ROWS = BLK / FO;
    __shared__ float Ws[FI * FO];
    __shared__ float Hs[ROWS * FI];
    __shared__ float sc[FI], sh[FI];
    int tid = threadIdx.x;
    for (int i = tid; i < FI * FO; i += BLK) Ws[i] = W[i];
    if (tid < FI) {
        const float invn = 1.0f / (float)Nn;
        float mu  = stat[tid] * invn;
        float var = stat[FI + tid] * invn - mu * mu;
        float kk  = g[tid] * rsqrtf(var + BN_EPS);
        sc[tid] = kk;
        sh[tid] = be[tid] - mu * kk;
    }
    __syncthreads();
    int node0 = blockIdx.x * ROWS;
    for (int i = tid; i < ROWS * FI; i += BLK) {
        int r = i / FI, f = i % FI;
        Hs[i] = fmaxf(acc[(node0 + r) * FI + f] * sc[f] + sh[f], 0.f);
    }
    __syncthreads();
    int fo = tid % FO, r = tid / FO;
    int node = node0 + r;
    float a = 0.f;
#pragma unroll
    for (int fi = 0; fi < FI; fi++) a += Hs[r * FI + fi] * Ws[fi * FO + fo];
    a *= g_dinv[node];
    out[node * FO + fo] = __float2half_rn(a);
}

// was[k][h] = sum_c Wg[k][h*16+c]*att_src[h][c]; wad likewise. 128 threads.
__global__ void k_prep(const float* __restrict__ Wg, const float* __restrict__ asrc,
                       const float* __restrict__ adst) {
    int t = threadIdx.x;
    int k = t >> 3, h = t & 7;
    float s1 = 0.f, s2 = 0.f;
#pragma unroll
    for (int c = 0; c < 16; c++) {
        float w = Wg[k * 128 + h * 16 + c];
        s1 += w * asrc[h * 16 + c];
        s2 += w * adst[h * 16 + c];
    }
    g_was[k * 8 + h] = s1;
    g_wad[k * 8 + h] = s2;
}

// fused BN+ReLU(layer3) + h3->half + attention dots. block=256 -> 16 nodes. Nn%16==0.
__global__ void k_bn3att(const float* __restrict__ acc3, const float* __restrict__ stat,
                         const float* __restrict__ g, const float* __restrict__ be) {
    __shared__ float sv[16][17];
    __shared__ float sw[2][16][8];
    int t = threadIdx.x;
    if (t < 128) { sw[0][t >> 3][t & 7] = g_was[t]; sw[1][t >> 3][t & 7] = g_wad[t]; }
    int node0 = blockIdx.x * 16;
    int nl = t >> 4, f = t & 15;
    const float invn = 1.0f / (float)Nn;
    float mu  = stat[f] * invn;
    float var = stat[16 + f] * invn - mu * mu;
    float v = (acc3[(node0 + nl) * 16 + f] - mu) * rsqrtf(var + BN_EPS) * g[f] + be[f];
    v = fmaxf(v, 0.f);
    sv[nl][f] = v;
    __syncthreads();
    if (t < 64) {
        int n2 = t >> 2, q = t & 3;
        __half2 p0 = __floats2half2_rn(sv[n2][q * 4 + 0], sv[n2][q * 4 + 1]);
        __half2 p1 = __floats2half2_rn(sv[n2][q * 4 + 2], sv[n2][q * 4 + 3]);
        uint2 u;
        u.x = *(unsigned*)&p0;
        u.y = *(unsigned*)&p1;
        g_h3h[(node0 + n2) * 4 + q] = u;
    }
    if (t < 128) {
        int n3 = t >> 3, h = t & 7;
        float s1 = 0.f, s2 = 0.f;
#pragma unroll
        for (int k = 0; k < 16; k++) {
            float hv = sv[n3][k];
            s1 += hv * sw[0][k][h];
            s2 += hv * sw[1][k][h];
        }
        g_as[(node0 + n3) * 8 + h] = s1;
        g_ad[(node0 + n3) * 8 + h] = s2;
    }
}

// ---------------- fused GAT (single-pass online softmax, 2-stage pipeline) ----------------
__device__ __forceinline__ void gat_step(float l, uint2 u, float& m, float& sum, float4& acc) {
    float2 f0 = __half22float2(*(const __half2*)&u.x);
    float2 f1 = __half22float2(*(const __half2*)&u.y);
    float d = l - m;
    float e = __expf(-fabsf(d));
    if (d <= 0.f) {
        sum += e;
        acc.x += e * f0.x; acc.y += e * f0.y; acc.z += e * f1.x; acc.w += e * f1.y;
    } else {
        sum = sum * e + 1.f;
        acc.x = acc.x * e + f0.x; acc.y = acc.y * e + f0.y;
        acc.z = acc.z * e + f1.x; acc.w = acc.w * e + f1.y;
        m = l;
    }
}

__global__ void k_gat(const float* __restrict__ Wg, const float* __restrict__ bg,
                      const int* __restrict__ batch) {
    __shared__ float Wgs[16 * 128];
    __shared__ float buf[8][8][16];     // [warp][head][k]
    for (int i = threadIdx.x; i < 16 * 128; i += blockDim.x) Wgs[i] = Wg[i];
    __syncthreads();
    int lane = threadIdx.x & 31, warp = threadIdx.x >> 5;
    int d = blockIdx.x * 8 + warp;      // grid = Nn/8 exact
    int h = lane >> 2, j = lane & 3;
    float adh = g_ad[d * 8 + h];
    int r0 = g_row[d], r1 = g_row[d + 1];

    // init with self edge
    float m = leaky(g_as[d * 8 + h] + adh);
    float sum = 1.f;
    uint2 su = __ldg(&g_h3h[d * 4 + j]);
    float2 sf0 = __half22float2(*(const __half2*)&su.x);
    float2 sf1 = __half22float2(*(const __half2*)&su.y);
    float4 acc = make_float4(sf0.x, sf0.y, sf1.x, sf1.y);

    int nb = (r1 - r0) >> 2;
    int k = r0 + (nb << 2);             // tail start
    if (nb >= 2) {
        int p0 = __ldg(&g_csrc[r0]),     p1 = __ldg(&g_csrc[r0 + 1]);
        int p2 = __ldg(&g_csrc[r0 + 2]), p3 = __ldg(&g_csrc[r0 + 3]);
        int q0 = __ldg(&g_csrc[r0 + 4]), q1 = __ldg(&g_csrc[r0 + 5]);
        int q2 = __ldg(&g_csrc[r0 + 6]), q3 = __ldg(&g_csrc[r0 + 7]);
        float la0 = __ldg(&g_as[p0 * 8 + h]), la1 = __ldg(&g_as[p1 * 8 + h]);
        float la2 = __ldg(&g_as[p2 * 8 + h]), la3 = __ldg(&g_as[p3 * 8 + h]);
        uint2 ua0 = __ldg(&g_h3h[p0 * 4 + j]);
        uint2 ua1 = __ldg(&g_h3h[p1 * 4 + j]);
        uint2 ua2 = __ldg(&g_h3h[p2 * 4 + j]);
        uint2 ua3 = __ldg(&g_h3h[p3 * 4 + j]);
        for (int t = 0; t < nb - 1; t++) {
            int c0, c1, c2, c3;
            bool more = (t + 2) < nb;
            if (more) {
                int base = r0 + (t + 2) * 4;
                c0 = __ldg(&g_csrc[base]);     c1 = __ldg(&g_csrc[base + 1]);
                c2 = __ldg(&g_csrc[base + 2]); c3 = __ldg(&g_csrc[base + 3]);
            }
            float lb0 = __ldg(&g_as[q0 * 8 + h]), lb1 = __ldg(&g_as[q1 * 8 + h]);
            float lb2 = __ldg(&g_as[q2 * 8 + h]), lb3 = __ldg(&g_as[q3 * 8 + h]);
            uint2 ub0 = __ldg(&g_h3h[q0 * 4 + j]);
            uint2 ub1 = __ldg(&g_h3h[q1 * 4 + j]);
            uint2 ub2 = __ldg(&g_h3h[q2 * 4 + j]);
            uint2 ub3 = __ldg(&g_h3h[q3 * 4 + j]);
            gat_step(leaky(la0 + adh), ua0, m, sum, acc);
            gat_step(leaky(la1 + adh), ua1, m, sum, acc);
            gat_step(leaky(la2 + adh), ua2, m, sum, acc);
            gat_step(leaky(la3 + adh), ua3, m, sum, acc);
            la0 = lb0; la1 = lb1; la2 = lb2; la3 = lb3;
            ua0 = ub0; ua1 = ub1; ua2 = ub2; ua3 = ub3;
            if (more) { q0 = c0; q1 = c1; q2 = c2; q3 = c3; }
        }
        gat_step(leaky(la0 + adh), ua0, m, sum, acc);
        gat_step(leaky(la1 + adh), ua1, m, sum, acc);
        gat_step(leaky(la2 + adh), ua2, m, sum, acc);
        gat_step(leaky(la3 + adh), ua3, m, sum, acc);
    } else if (nb == 1) {
        int p0 = __ldg(&g_csrc[r0]),     p1 = __ldg(&g_csrc[r0 + 1]);
        int p2 = __ldg(&g_csrc[r0 + 2]), p3 = __ldg(&g_csrc[r0 + 3]);
        float la0 = __ldg(&g_as[p0 * 8 + h]), la1 = __ldg(&g_as[p1 * 8 + h]);
        float la2 = __ldg(&g_as[p2 * 8 + h]), la3 = __ldg(&g_as[p3 * 8 + h]);
        uint2 ua0 = __ldg(&g_h3h[p0 * 4 + j]);
        uint2 ua1 = __ldg(&g_h3h[p1 * 4 + j]);
        uint2 ua2 = __ldg(&g_h3h[p2 * 4 + j]);
        uint2 ua3 = __ldg(&g_h3h[p3 * 4 + j]);
        gat_step(leaky(la0 + adh), ua0, m, sum, acc);
        gat_step(leaky(la1 + adh), ua1, m, sum, acc);
        gat_step(leaky(la2 + adh), ua2, m, sum, acc);
        gat_step(leaky(la3 + adh), ua3, m, sum, acc);
    }
    for (; k < r1; k++) {
        int s = __ldg(&g_csrc[k]);
        float l = leaky(__ldg(&g_as[s * 8 + h]) + adh);
        gat_step(l, __ldg(&g_h3h[s * 4 + j]), m, sum, acc);
    }
    float sc = 0.125f / sum;  // alpha-normalize + head-mean
    buf[warp][h][j * 4 + 0] = acc.x * sc;
    buf[warp][h][j * 4 + 1] = acc.y * sc;
    buf[warp][h][j * 4 + 2] = acc.z * sc;
    buf[warp][h][j * 4 + 3] = acc.w * sc;
    __syncwarp();

    // mini-GEMM: hg[c] = bg[c] + sum_h sum_k buf[h][k]*Wg[k][h*16+c]; then pool
    if (lane < 4) {
        float4 hg = ((const float4*)bg)[lane];
#pragma unroll
        for (int hh = 0; hh < 8; hh++) {
#pragma unroll
            for (int kk = 0; kk < 16; kk++) {
                float a = buf[warp][hh][kk];
                const float4 w = *(const float4*)&Wgs[kk * 128 + hh * 16 + lane * 4];
                hg.x += a * w.x; hg.y += a * w.y; hg.z += a * w.z; hg.w += a * w.w;
            }
        }
        red4(((float4*)g_pool) + batch[d] * 4 + lane, hg);
    }
}

__global__ void k_final(const float* __restrict__ Wf, const float* __restrict__ bf,
                        float* __restrict__ out) {
    int i = blockIdx.x * blockDim.x + threadIdx.x;
    if (i >= Gg * 3) return;
    int gg = i / 3, k = i % 3;
    float s = bf[k];
#pragma unroll
    for (int c = 0; c < 16; c++) s += g_pool[gg * 16 + c] * Wf[c * 3 + k];
    out[i] = s;
}

// ---------------- launch ----------------
static inline void* symaddr(const void* s) { void* p = nullptr; cudaGetSymbolAddress(&p, s); return p; }

extern "C" void kernel_launch(void* const* d_in, const int* in_sizes, int n_in,
                              void* d_out, int out_size) {
    const float* x       = (const float*)d_in[0];
    const int*   ei      = (const int*)  d_in[1];
    const int*   batch   = (const int*)  d_in[2];
    const float* W1 = (const float*)d_in[3],  *b1 = (const float*)d_in[4];
    const float* g1 = (const float*)d_in[5],  *be1= (const float*)d_in[6];
    const float* W2 = (const float*)d_in[7],  *b2 = (const float*)d_in[8];
    const float* g2 = (const float*)d_in[9],  *be2= (const float*)d_in[10];
    const float* W3 = (const float*)d_in[11], *b3 = (const float*)d_in[12];
    const float* g3 = (const float*)d_in[13], *be3= (const float*)d_in[14];
    const float* Wg = (const float*)d_in[15];
    const float* att_src = (const float*)d_in[16];
    const float* att_dst = (const float*)d_in[17];
    const float* bg = (const float*)d_in[18];
    const float* Wf = (const float*)d_in[19], *bf = (const float*)d_in[20];
    float* out = (float*)d_out;
    const int E = in_sizes[1] / 2;

    float* axp  = (float*)symaddr(g_axp);
    float* acc1 = (float*)symaddr(g_acc1);
    float* acc2 = (float*)symaddr(g_acc2);
    float* acc3 = (float*)symaddr(g_acc3);
    float* bn   = (float*)symaddr(g_bn);
    uint4* xh   = (uint4*)symaddr(g_xh);
    uint4* t2h  = (uint4*)symaddr(g_t2h);
    uint4* t3h  = (uint4*)symaddr(g_t3h);

    const int B = 256;
    // ---- CSR build ----
    k_init<<<(Nn + B - 1) / B, B>>>();
    k_deg<<<(E / 4 + B) / B, B>>>(ei, E);
    k_scan<<<1, 1024>>>();
    k_fill<<<(E / 4 + B) / B, B>>>(ei, E);
    k_convx<<<(Nn * 32 + B - 1) / B, B>>>(x);

    // ---- GCN layer 1: aggregate x' (half), GEMM 20->64 (+stats) ----
    k_gcn<4, false><<<(Nn + 63) / 64, B>>>(xh, nullptr, (float4*)axp, nullptr);
    k_gemm1<<<Nn / 8, 512>>>(axp, W1, b1, acc1, bn + 0);

    // ---- GCN layer 2: fused BN1+ReLU+GEMM 64->32 (*dinv, half), aggregate (+stats) ----
    k_gemmbn<64, 32><<<Nn / 16, 512>>>(acc1, bn + 0, g1, be1, W2, (__half*)t2h);
    k_gcn<4, true><<<(Nn + 63) / 64, B>>>(t2h, b2, (float4*)acc2, bn + 128);

    // ---- GCN layer 3: fused BN2+ReLU+GEMM 32->16 (*dinv, half), aggregate (+stats) ----
    k_gemmbn<32, 16><<<Nn / 32, 512>>>(acc2, bn + 128, g2, be2, W3, (__half*)t3h);
    k_gcn<2, true><<<(Nn + 127) / 128, B>>>(t3h, b3, (float4*)acc3, bn + 256);

    // ---- BN3 + attention dots fused, then single-pass GAT ----
    k_prep<<<1, 128>>>(Wg, att_src, att_dst);
    k_bn3att<<<Nn / 16, B>>>(acc3, bn + 256, g3, be3);
    k_gat<<<Nn / 8, B>>>(Wg, bg, batch);

    // ---- classifier ----
    k_final<<<(Gg * 3 + B - 1) / B, B>>>(Wf, bf, out);
}